// round 1
// baseline (speedup 1.0000x reference)
#include <cuda_runtime.h>
#include <math.h>

#define T_LEN 262144
#define B_N 8
#define C_N 8
#define K_N 50
#define TILE_T 512
#define THREADS 128
#define NPOS 4

// Ping-pong hidden-state buffers [B][C][T] and normalized weights [18][K][C][O]
__device__ float g_h0[B_N * C_N * T_LEN];
__device__ float g_h1[B_N * C_N * T_LEN];
__device__ float g_W[18 * K_N * C_N * C_N];

// ---------------------------------------------------------------------------
// Weight-norm prep: one block per (layer, out-channel).
// w[o,c,k] = g[o] * v[o,c,k] / sqrt(sum_{c,k} v^2), stored as [layer][k][c][o].
// ---------------------------------------------------------------------------
__global__ void prep_weights(const float* __restrict__ v0,
                             const float* __restrict__ g0,
                             const float* __restrict__ vs,
                             const float* __restrict__ gs) {
    int l = blockIdx.x;   // 0..17
    int o = blockIdx.y;   // 0..7
    int cin = (l == 0) ? 1 : C_N;
    const float* v;
    float g;
    if (l == 0) {
        v = v0 + o * K_N;               // [C,1,K]
        g = g0[o];
    } else {
        v = vs + (size_t)((l - 1) * C_N + o) * C_N * K_N;  // [17,C,C,K]
        g = gs[(l - 1) * C_N + o];
    }
    int n = cin * K_N;
    float s = 0.0f;
    for (int i = threadIdx.x; i < n; i += blockDim.x) {
        float x = v[i];
        s += x * x;
    }
    __shared__ float red[2];
    #pragma unroll
    for (int off = 16; off > 0; off >>= 1)
        s += __shfl_down_sync(0xffffffffu, s, off);
    if ((threadIdx.x & 31) == 0) red[threadIdx.x >> 5] = s;
    __syncthreads();
    float scale = g * rsqrtf(red[0] + red[1]);
    float* W = g_W + (size_t)l * K_N * C_N * C_N;
    for (int i = threadIdx.x; i < n; i += blockDim.x) {
        int c = i / K_N;
        int k = i % K_N;
        W[(k * C_N + c) * C_N + o] = scale * v[i];
    }
}

// ---------------------------------------------------------------------------
// One residual gated-conv block.
//   out[o,t] = b[o] + sum_{c,k} w[o,c,k] * h[c, t-(K-1-k)*d]
//   gate[o,t]= gb[o] + sum_c gw[o,c] * out[c,t]
//   h'[o,t]  = tanh(out) * sigmoid(gate) + h[(FIRST?0:o), t]
// Block: 128 threads, 512-time tile, 4 positions/thread strided by 128
// (lane-consecutive SMEM reads -> conflict-free).
// ---------------------------------------------------------------------------
__device__ __forceinline__ float fast_tanh(float x) {
    x = fminf(fmaxf(x, -30.0f), 30.0f);
    float e = __expf(-2.0f * x);
    return (1.0f - e) / (1.0f + e);
}
__device__ __forceinline__ float fast_sigmoid(float x) {
    x = fminf(fmaxf(x, -30.0f), 30.0f);
    return 1.0f / (1.0f + __expf(-x));
}

template <int DIL, bool FIRST>
__global__ void __launch_bounds__(THREADS)
layer_kernel(const float* __restrict__ h_in, float* __restrict__ h_out,
             const float* __restrict__ W,     // [K][8][8] (c-dim stride 8 always)
             const float* __restrict__ bias,  // [8]
             const float* __restrict__ gw,    // [8][8]
             const float* __restrict__ gb) {  // [8]
    constexpr int CIN = FIRST ? 1 : C_N;
    constexpr int HALO = (K_N - 1) * DIL;
    constexpr int HW = TILE_T + HALO;

    __shared__ __align__(16) float h_s[CIN][HW];
    __shared__ __align__(16) float w_s[K_N][CIN][C_N];
    __shared__ float gw_s[C_N][C_N];
    __shared__ float b_s[C_N];
    __shared__ float gb_s[C_N];

    const int b = blockIdx.y;
    const int tile0 = blockIdx.x * TILE_T;
    const int tid = threadIdx.x;

    // Stage weights (w_s[k][c][o] <- W[k*64 + c*8 + o]; for FIRST c==0 only).
    for (int i = tid; i < K_N * CIN * C_N; i += THREADS) {
        int k = i / (CIN * C_N);
        int r = i - k * (CIN * C_N);
        (&w_s[0][0][0])[i] = W[k * (C_N * C_N) + r];
    }
    for (int i = tid; i < C_N * C_N; i += THREADS) (&gw_s[0][0])[i] = gw[i];
    if (tid < C_N) { b_s[tid] = bias[tid]; gb_s[tid] = gb[tid]; }

    // Stage h tile with causal zero pad.
    const float* hb = h_in + (size_t)b * CIN * T_LEN;
    for (int i = tid; i < CIN * HW; i += THREADS) {
        int c = i / HW;
        int j = i - c * HW;
        int t = tile0 - HALO + j;
        h_s[c][j] = (t >= 0) ? hb[(size_t)c * T_LEN + t] : 0.0f;
    }
    __syncthreads();

    float acc[C_N][NPOS];
    #pragma unroll
    for (int o = 0; o < C_N; o++) {
        float bv = b_s[o];
        #pragma unroll
        for (int p = 0; p < NPOS; p++) acc[o][p] = bv;
    }

    #pragma unroll 1
    for (int k = 0; k < K_N; k++) {
        const int base = tid + k * DIL;
        #pragma unroll
        for (int c = 0; c < CIN; c++) {
            float hv[NPOS];
            #pragma unroll
            for (int p = 0; p < NPOS; p++) hv[p] = h_s[c][base + p * THREADS];
            float wv[C_N];
            *(float4*)&wv[0] = *(const float4*)&w_s[k][c][0];
            *(float4*)&wv[4] = *(const float4*)&w_s[k][c][4];
            #pragma unroll
            for (int o = 0; o < C_N; o++)
                #pragma unroll
                for (int p = 0; p < NPOS; p++)
                    acc[o][p] = fmaf(wv[o], hv[p], acc[o][p]);
        }
    }

    // Gating + residual + store.
    float* ob = h_out + (size_t)b * C_N * T_LEN;
    #pragma unroll
    for (int o = 0; o < C_N; o++) {
        #pragma unroll
        for (int p = 0; p < NPOS; p++) {
            float gate = gb_s[o];
            #pragma unroll
            for (int c = 0; c < C_N; c++) gate = fmaf(gw_s[o][c], acc[c][p], gate);
            float prev = h_s[FIRST ? 0 : o][tid + HALO + p * THREADS];
            float r = fast_tanh(acc[o][p]) * fast_sigmoid(gate) + prev;
            ob[(size_t)o * T_LEN + tile0 + tid + p * THREADS] = r;
        }
    }
}

// ---------------------------------------------------------------------------
// Head: means = mean_w . h + mean_b ; stds = exp(0.5*(lv_w . h + lv_b))
// out layout: [means (B*T), stds (B*T)]
// ---------------------------------------------------------------------------
__global__ void __launch_bounds__(256)
head_kernel(const float* __restrict__ h,
            const float* __restrict__ mean_w, const float* __restrict__ mean_b,
            const float* __restrict__ lv_w, const float* __restrict__ lv_b,
            float* __restrict__ out) {
    const int b = blockIdx.y;
    const int t0 = (blockIdx.x * 256 + threadIdx.x) * 4;
    if (t0 >= T_LEN) return;
    const float* hb = h + (size_t)b * C_N * T_LEN;
    float m[4], lv[4];
    float mb = mean_b[0], lb = lv_b[0];
    #pragma unroll
    for (int p = 0; p < 4; p++) { m[p] = mb; lv[p] = lb; }
    #pragma unroll
    for (int c = 0; c < C_N; c++) {
        float4 hv = *(const float4*)&hb[(size_t)c * T_LEN + t0];
        float mw = mean_w[c], lw = lv_w[c];
        m[0] = fmaf(mw, hv.x, m[0]); lv[0] = fmaf(lw, hv.x, lv[0]);
        m[1] = fmaf(mw, hv.y, m[1]); lv[1] = fmaf(lw, hv.y, lv[1]);
        m[2] = fmaf(mw, hv.z, m[2]); lv[2] = fmaf(lw, hv.z, lv[2]);
        m[3] = fmaf(mw, hv.w, m[3]); lv[3] = fmaf(lw, hv.w, lv[3]);
    }
    float s[4];
    #pragma unroll
    for (int p = 0; p < 4; p++) s[p] = expf(0.5f * lv[p]);
    *(float4*)&out[(size_t)b * T_LEN + t0] = make_float4(m[0], m[1], m[2], m[3]);
    *(float4*)&out[(size_t)B_N * T_LEN + (size_t)b * T_LEN + t0] =
        make_float4(s[0], s[1], s[2], s[3]);
}

// ---------------------------------------------------------------------------
extern "C" void kernel_launch(void* const* d_in, const int* in_sizes, int n_in,
                              void* d_out, int out_size) {
    (void)in_sizes; (void)n_in; (void)out_size;
    const float* x      = (const float*)d_in[0];
    const float* v0     = (const float*)d_in[1];
    const float* g0     = (const float*)d_in[2];
    const float* b0     = (const float*)d_in[3];
    const float* gw0    = (const float*)d_in[4];
    const float* gb0    = (const float*)d_in[5];
    const float* vs     = (const float*)d_in[6];
    const float* gs     = (const float*)d_in[7];
    const float* bs     = (const float*)d_in[8];
    const float* gws    = (const float*)d_in[9];
    const float* gbs    = (const float*)d_in[10];
    const float* mean_w = (const float*)d_in[11];
    const float* mean_b = (const float*)d_in[12];
    const float* lv_w   = (const float*)d_in[13];
    const float* lv_b   = (const float*)d_in[14];

    float *bufA, *bufB, *Wdev;
    cudaGetSymbolAddress((void**)&bufA, g_h0);
    cudaGetSymbolAddress((void**)&bufB, g_h1);
    cudaGetSymbolAddress((void**)&Wdev, g_W);

    prep_weights<<<dim3(18, 8), 64>>>(v0, g0, vs, gs);

    dim3 grid(T_LEN / TILE_T, B_N);

    // Layer 0 (C_in = 1, dilation 1)
    layer_kernel<1, true><<<grid, THREADS>>>(x, bufA, Wdev, b0, gw0, gb0);

    static const int dils[18] = {1,1,1,1,1,1,1,2,2,2,2,4,4,4,4,8,8,8};
    float* cur = bufA;
    float* nxt = bufB;
    for (int i = 1; i < 18; i++) {
        const float* Wl  = Wdev + (size_t)i * K_N * C_N * C_N;
        const float* bl  = bs  + (i - 1) * C_N;
        const float* gwl = gws + (i - 1) * C_N * C_N;
        const float* gbl = gbs + (i - 1) * C_N;
        switch (dils[i]) {
            case 1: layer_kernel<1, false><<<grid, THREADS>>>(cur, nxt, Wl, bl, gwl, gbl); break;
            case 2: layer_kernel<2, false><<<grid, THREADS>>>(cur, nxt, Wl, bl, gwl, gbl); break;
            case 4: layer_kernel<4, false><<<grid, THREADS>>>(cur, nxt, Wl, bl, gwl, gbl); break;
            case 8: layer_kernel<8, false><<<grid, THREADS>>>(cur, nxt, Wl, bl, gwl, gbl); break;
        }
        float* t = cur; cur = nxt; nxt = t;
    }

    head_kernel<<<dim3(T_LEN / (256 * 4), B_N), 256>>>(
        cur, mean_w, mean_b, lv_w, lv_b, (float*)d_out);
}